// round 11
// baseline (speedup 1.0000x reference)
#include <cuda_runtime.h>

// ---------------------------------------------------------------------------
// ResonantComplexProjection
//   theta[b,n,i] = x[b,i] / (1+|W[n,i]|) + B[n,i]
//   idx = floor(theta * 4096/2pi) mod 4096   (LUT sin/cos, 4096 entries)
//   cos_sum[b,n] = sum_i cos_lut[idx];  sin_sum likewise
//   real = cos_sum @ Wr^T ; imag = sin_sum @ Wi^T
// Shapes: batch=256, in_f=512, n_neur=1024, out_f=512
// ---------------------------------------------------------------------------

#define LUT_HALF 4608                  // table covers k in [-4608, 4608)
#define LUT_N    (2 * LUT_HALF)        // 9216 packed entries {cos16|sin16}
#define SMEM_MAIN (LUT_N * 4 + 2048)   // 36KB LUT + 2KB x tile = 38912 B
#define LUT_SCALE 16384.0f             // int16 quantization scale (2^14)

static __device__ unsigned g_lut32[LUT_N];     // {(s16)(cos*16384)<<16 | (u16)(s16)(sin*16384)}
static __device__ float4 g_rsbs[256 * 1024];   // [ipair][n] -> {rs0, rs1, bs0, bs1}
static __device__ int2   g_sums[4 * 262144];   // [iq][b][n] -> (sin_acc, cos_acc) int32
static __device__ float  g_A[2 * 262144];      // [p][b][k]: p0=cos, p1=sin
static __device__ float  g_part[16][262144];   // [ksplit][p*131072 + b*512 + o]

// ---------------------------------------------------------------------------
// Fused init: blocks [0,18) build the int16 LUT; blocks [18,1042) build rs/bs.
// ---------------------------------------------------------------------------

__global__ void k_init(const float* __restrict__ W, const float* __restrict__ B) {
    const int bid = blockIdx.x;
    const int tid = threadIdx.x;
    if (bid < 18) {
        int t = bid * 256 + tid;                   // < 4608
        const float step = (float)(6.283185307179586476925287 / 4096.0);
        int k0 = 2 * t - LUT_HALF;
        int j0 = k0 & 4095;                        // floor-mod 4096 (matches Python %)
        int j1 = (k0 + 1) & 4095;
        float a0 = (float)j0 * step;
        float a1 = (float)j1 * step;
        int s0 = __float2int_rn(sinf(a0) * LUT_SCALE);   // |v| <= 16384, fits s16
        int c0 = __float2int_rn(cosf(a0) * LUT_SCALE);
        int s1 = __float2int_rn(sinf(a1) * LUT_SCALE);
        int c1 = __float2int_rn(cosf(a1) * LUT_SCALE);
        unsigned w0 = ((unsigned)(unsigned short)(short)c0 << 16) | (unsigned short)(short)s0;
        unsigned w1 = ((unsigned)(unsigned short)(short)c1 << 16) | (unsigned short)(short)s1;
        ((uint2*)g_lut32)[t] = make_uint2(w0, w1);
    } else {
        int e = (bid - 18) * 256 + tid;            // < 262144
        int n  = e & 1023;
        int ip = e >> 10;
        const float S = (float)(4096.0 / 6.283185307179586476925287);
        float2 w = ((const float2*)(W + n * 512))[ip];
        float2 b = ((const float2*)(B + n * 512))[ip];
        float4 v;
        v.x = S / (1.0f + fabsf(w.x));
        v.y = S / (1.0f + fabsf(w.y));
        v.z = S * b.x - 0.5f;                      // fold floor(v)=round(v-0.5) shift
        v.w = S * b.y - 0.5f;
        g_rsbs[e] = v;                             // e = ip*1024 + n
    }
}

// ---------------------------------------------------------------------------
// Packed helpers
// ---------------------------------------------------------------------------

__device__ __forceinline__ unsigned long long fma2_(unsigned long long a,
                                                    unsigned long long b,
                                                    unsigned long long c) {
    unsigned long long d;
    asm("fma.rn.f32x2 %0, %1, %2, %3;" : "=l"(d) : "l"(a), "l"(b), "l"(c));
    return d;
}
__device__ __forceinline__ unsigned long long add2_(unsigned long long a,
                                                    unsigned long long b) {
    unsigned long long d;
    asm("add.rn.f32x2 %0, %1, %2;" : "=l"(d) : "l"(a), "l"(b));
    return d;
}
__device__ __forceinline__ unsigned lds32_(unsigned a) {
    unsigned v;
    asm("ld.shared.b32 %0, [%1];" : "=r"(v) : "r"(a));
    return v;
}
// dp2a.lo: d = a.h0*b.b0 + a.h1*b.b1 + c  (16-bit halves of a, low 2 bytes of b)
__device__ __forceinline__ int dp2a_(unsigned a, unsigned b, int c) {
    int d;
    asm("dp2a.lo.s32.s32 %0, %1, %2, %3;" : "=r"(d) : "r"(a), "r"(b), "r"(c));
    return d;
}

// ---------------------------------------------------------------------------
// k_main (UNCHANGED — proven R9): 296 blocks, strided 1024 fine tiles,
// thread = 1 neuron x 4 batches; int16 LUT gathered via LDS.32 and
// accumulated exactly in int32 via dp2a. Magic-floor addressing.
// ---------------------------------------------------------------------------

__global__ __launch_bounds__(256, 2) void k_main(const float* __restrict__ x) {
    extern __shared__ unsigned char smem[];
    uint4* lutv = (uint4*)smem;
    unsigned long long* xs2 = (unsigned long long*)(smem + LUT_N * 4);  // [4 b][64 ip]

    const int tid = threadIdx.x;

#pragma unroll
    for (int t = 0; t < (LUT_N / 4) / 256; t++)        // stage 36KB LUT (9 iters)
        lutv[tid + t * 256] = ((const uint4*)g_lut32)[tid + t * 256];

    const unsigned cbase =
        (unsigned)__cvta_generic_to_shared(smem) + (unsigned)(LUT_HALF * 4) - 0x2D000000u;
    const unsigned long long MAGIC2 = 0x4B4000004B400000ULL;
    const unsigned SEL_S = 0x00000001u;   // dp2a: take low half (sin)
    const unsigned SEL_C = 0x00000100u;   // dp2a: take high half (cos)

    const int lb  = tid >> 6;            // x-loader batch 0..3
    const int ipl = tid & 63;            // x-loader ipair 0..63

    for (int t = blockIdx.x; t < 1024; t += 296) {
        const int nt = t & 3;
        const int iq = (t >> 2) & 3;     // i-quarter (64 ipairs)
        const int bg = t >> 4;           // batch group of 4 (0..63)

        __syncthreads();                 // protect xs2 readers of previous tile
        xs2[tid] = ((const unsigned long long*)x)[((bg << 2) + lb) * 256 + (iq << 6) + ipl];
        __syncthreads();

        const int n = (nt << 8) + tid;
        const ulonglong2* rb =
            (const ulonglong2*)g_rsbs + (size_t)(iq << 6) * 1024 + n;

        int accS[4], accC[4];
#pragma unroll
        for (int b = 0; b < 4; b++) { accS[b] = 0; accC[b] = 0; }

#pragma unroll 2
        for (int ip = 0; ip < 64; ip++) {
            ulonglong2 rv = __ldg(rb + ip * 1024);    // {rs0,rs1},{bs0,bs1}
#pragma unroll
            for (int b = 0; b < 4; b++) {
                unsigned long long xp = xs2[(b << 6) + ip];   // bcast LDS.64
                unsigned long long w  = add2_(fma2_(xp, rv.x, rv.y), MAGIC2);
                unsigned qlo, qhi;
                asm("mov.b64 {%0, %1}, %2;" : "=r"(qlo), "=r"(qhi) : "l"(w));
                unsigned e0 = lds32_(qlo * 4u + cbase);       // {cos16|sin16}
                unsigned e1 = lds32_(qhi * 4u + cbase);
                accS[b] = dp2a_(e0, SEL_S, accS[b]);
                accC[b] = dp2a_(e0, SEL_C, accC[b]);
                accS[b] = dp2a_(e1, SEL_S, accS[b]);
                accC[b] = dp2a_(e1, SEL_C, accC[b]);
            }
        }

        int2* sp = g_sums + (size_t)iq * 262144 + (size_t)(bg << 2) * 1024 + n;
#pragma unroll
        for (int b = 0; b < 4; b++) sp[(size_t)b * 1024] = make_int2(accS[b], accC[b]);
    }
}

// ---------------------------------------------------------------------------
// k_comb (UNCHANGED — proven): integer-sum 4 quarters exactly, scale once.
// ---------------------------------------------------------------------------

__global__ void k_comb() {
    int e = blockIdx.x * 256 + threadIdx.x;            // < 131072 int4s/quarter
    const int4* p0 = (const int4*)g_sums;              // {s0,c0,s1,c1}
    const int4* p1 = (const int4*)(g_sums + 262144);
    const int4* p2 = (const int4*)(g_sums + 2 * 262144);
    const int4* p3 = (const int4*)(g_sums + 3 * 262144);
    int4 a = p0[e], b = p1[e], c = p2[e], d = p3[e];
    int s0 = (a.x + b.x) + (c.x + d.x);
    int c0 = (a.y + b.y) + (c.y + d.y);
    int s1 = (a.z + b.z) + (c.z + d.z);
    int c1 = (a.w + b.w) + (c.w + d.w);
    const float SC = 1.0f / LUT_SCALE;
    ((float2*)g_A)[e]            = make_float2((float)c0 * SC, (float)c1 * SC); // cos
    ((float2*)(g_A + 262144))[e] = make_float2((float)s0 * SC, (float)s1 * SC); // sin
}

// ---------------------------------------------------------------------------
// k_gemm5: gemm4 skeleton (double-buffered, ONE sync per chunk, outer
// `#pragma unroll 1`) with exactly two changes:
//  (1) packed fma.rn.f32x2: A staged DUPLICATED {a,a} in smem (broadcast
//      operand -> duplication is crossbar-free on read), B natural pairs.
//      Inner kk: 3 LDS.128 + 8 FMA2 = 32 MACs per 11 issues.
//  (2) 16 K-splits (K=64 = 4 chunks/block), grid (4,8,32) = 1024 blocks:
//      3 short waves vs the old 2 long waves (73% -> ~30% wave slack,
//      wave>=2 work-steal smooths further).
// ---------------------------------------------------------------------------

#define BK  16
#define GPA 132   // duplicated-A row stride in floats (128 data + 4 pad)
#define GPB 68    // B row stride in floats

__global__ __launch_bounds__(256, 3) void k_gemm5(const float* __restrict__ Wr,
                                                  const float* __restrict__ Wi) {
    __shared__ float AsD[2][BK][GPA];
    __shared__ float Bs [2][BK][GPB];

    const int tid = threadIdx.x;
    const int b0 = blockIdx.x << 6;
    const int o0 = blockIdx.y << 6;
    const int z  = blockIdx.z;
    const int pp = z >> 4;               // 0=real(cos), 1=imag(sin)
    const int s  = z & 15;               // K-split (64 each)

    const float* Ap = g_A + pp * 262144;
    const float* Wp = pp ? Wi : Wr;

    const int tx = tid & 15, ty = tid >> 4;
    const int lm = tid >> 2;             // loader row 0..63
    const int lq = (tid & 3) << 2;       // loader k-quad {0,4,8,12}
    const int kbase = s << 6;

    const float4* ga = (const float4*)(Ap + (size_t)(b0 + lm) * 1024 + kbase + lq);
    const float4* gw = (const float4*)(Wp + (size_t)(o0 + lm) * 1024 + kbase + lq);

    unsigned long long acc[4][2];
#pragma unroll
    for (int i = 0; i < 4; i++) { acc[i][0] = 0ULL; acc[i][1] = 0ULL; }

    float4 a4 = ga[0];
    float4 w4 = gw[0];
#pragma unroll
    for (int q = 0; q < 4; q++) {
        float aq = q == 0 ? a4.x : q == 1 ? a4.y : q == 2 ? a4.z : a4.w;
        float wq = q == 0 ? w4.x : q == 1 ? w4.y : q == 2 ? w4.z : w4.w;
        *(float2*)&AsD[0][lq + q][2 * lm] = make_float2(aq, aq);
        Bs[0][lq + q][lm] = wq;
    }
    __syncthreads();

#pragma unroll 1
    for (int kc = 0; kc < 4; kc++) {
        const int cur = kc & 1;
        if (kc < 3) {                     // prefetch next chunk (in flight under FMAs)
            a4 = ga[4 * (kc + 1)];
            w4 = gw[4 * (kc + 1)];
        }
#pragma unroll
        for (int kk = 0; kk < BK; kk++) {
            ulonglong2 d01 = *(const ulonglong2*)&AsD[cur][kk][8 * ty];      // {a0,a0},{a1,a1}
            ulonglong2 d23 = *(const ulonglong2*)&AsD[cur][kk][8 * ty + 4];  // {a2,a2},{a3,a3}
            ulonglong2 bb  = *(const ulonglong2*)&Bs[cur][kk][4 * tx];       // {b0,b1},{b2,b3}
            acc[0][0] = fma2_(d01.x, bb.x, acc[0][0]);
            acc[0][1] = fma2_(d01.x, bb.y, acc[0][1]);
            acc[1][0] = fma2_(d01.y, bb.x, acc[1][0]);
            acc[1][1] = fma2_(d01.y, bb.y, acc[1][1]);
            acc[2][0] = fma2_(d23.x, bb.x, acc[2][0]);
            acc[2][1] = fma2_(d23.x, bb.y, acc[2][1]);
            acc[3][0] = fma2_(d23.y, bb.x, acc[3][0]);
            acc[3][1] = fma2_(d23.y, bb.y, acc[3][1]);
        }
        if (kc < 3) {
            const int nxt = cur ^ 1;      // other buffer: safe to fill pre-sync
#pragma unroll
            for (int q = 0; q < 4; q++) {
                float aq = q == 0 ? a4.x : q == 1 ? a4.y : q == 2 ? a4.z : a4.w;
                float wq = q == 0 ? w4.x : q == 1 ? w4.y : q == 2 ? w4.z : w4.w;
                *(float2*)&AsD[nxt][lq + q][2 * lm] = make_float2(aq, aq);
                Bs[nxt][lq + q][lm] = wq;
            }
            __syncthreads();              // one barrier per chunk
        }
    }

    float* dst = &g_part[s][pp * 131072 + (size_t)(b0 + (ty << 2)) * 512 + o0 + (tx << 2)];
#pragma unroll
    for (int i = 0; i < 4; i++) {
        float4 o;
        o.x = __uint_as_float((unsigned)(acc[i][0]));
        o.y = __uint_as_float((unsigned)(acc[i][0] >> 32));
        o.z = __uint_as_float((unsigned)(acc[i][1]));
        o.w = __uint_as_float((unsigned)(acc[i][1] >> 32));
        *(float4*)(dst + (size_t)i * 512) = o;
    }
}

// ---------------------------------------------------------------------------
// k_reduce v3: 16-way, float4-vectorized, fixed pairwise order (deterministic).
// Partials are 16MB total -> L2-resident right after gemm writes them.
// ---------------------------------------------------------------------------

__global__ void k_reduce(float* __restrict__ out) {
    int e = blockIdx.x * 256 + threadIdx.x;     // < 65536 float4s
    float4 q[8];
#pragma unroll
    for (int j = 0; j < 8; j++) {
        float4 a = ((const float4*)g_part[2 * j])[e];
        float4 b = ((const float4*)g_part[2 * j + 1])[e];
        q[j] = make_float4(a.x + b.x, a.y + b.y, a.z + b.z, a.w + b.w);
    }
#pragma unroll
    for (int st = 1; st < 8; st <<= 1)
#pragma unroll
        for (int j = 0; j < 8; j += 2 * st) {
            q[j].x += q[j + st].x; q[j].y += q[j + st].y;
            q[j].z += q[j + st].z; q[j].w += q[j + st].w;
        }
    ((float4*)out)[e] = q[0];
}

// ---------------------------------------------------------------------------

extern "C" void kernel_launch(void* const* d_in, const int* in_sizes, int n_in,
                              void* d_out, int out_size) {
    const float* x  = (const float*)d_in[0];
    const float* W  = (const float*)d_in[1];
    const float* B  = (const float*)d_in[2];
    const float* Wr = (const float*)d_in[3];
    const float* Wi = (const float*)d_in[4];
    float* out = (float*)d_out;

    cudaFuncSetAttribute(k_main, cudaFuncAttributeMaxDynamicSharedMemorySize, SMEM_MAIN);

    k_init<<<18 + 1024, 256>>>(W, B);
    k_main<<<296, 256, SMEM_MAIN>>>(x);
    k_comb<<<512, 256>>>();
    k_gemm5<<<dim3(4, 8, 32), 256>>>(Wr, Wi);
    k_reduce<<<256, 256>>>(out);
}

// round 12
// speedup vs baseline: 1.0747x; 1.0747x over previous
#include <cuda_runtime.h>

// ---------------------------------------------------------------------------
// ResonantComplexProjection
//   theta[b,n,i] = x[b,i] / (1+|W[n,i]|) + B[n,i]
//   idx = floor(theta * 4096/2pi) mod 4096   (LUT sin/cos, 4096 entries)
//   cos_sum[b,n] = sum_i cos_lut[idx];  sin_sum likewise
//   real = cos_sum @ Wr^T ; imag = sin_sum @ Wi^T
// Shapes: batch=256, in_f=512, n_neur=1024, out_f=512
// ---------------------------------------------------------------------------

#define LUT_HALF 4608                  // table covers k in [-4608, 4608)
#define LUT_N    (2 * LUT_HALF)        // 9216 packed entries {cos16|sin16}
#define SMEM_MAIN (LUT_N * 4 + 2048)   // 36KB LUT + 2KB x tile = 38912 B
#define LUT_SCALE 16384.0f             // int16 quantization scale (2^14)

static __device__ unsigned g_lut32[LUT_N];     // {(s16)(cos*16384)<<16 | (u16)(s16)(sin*16384)}
static __device__ float4 g_rsbs[256 * 1024];   // [ipair][n] -> {rs0, rs1, bs0, bs1}
static __device__ int2   g_sums[4 * 262144];   // [iq][b][n] -> (sin_acc, cos_acc) int32
static __device__ float  g_A[2 * 262144];      // [p][b][k]: p0=cos, p1=sin
static __device__ float  g_part[8][262144];    // [ksplit][p*131072 + b*512 + o]

// ---------------------------------------------------------------------------
// Fused init: blocks [0,18) build the int16 LUT; blocks [18,1042) build rs/bs.
// ---------------------------------------------------------------------------

__global__ void k_init(const float* __restrict__ W, const float* __restrict__ B) {
    const int bid = blockIdx.x;
    const int tid = threadIdx.x;
    if (bid < 18) {
        int t = bid * 256 + tid;                   // < 4608
        const float step = (float)(6.283185307179586476925287 / 4096.0);
        int k0 = 2 * t - LUT_HALF;
        int j0 = k0 & 4095;                        // floor-mod 4096 (matches Python %)
        int j1 = (k0 + 1) & 4095;
        float a0 = (float)j0 * step;
        float a1 = (float)j1 * step;
        int s0 = __float2int_rn(sinf(a0) * LUT_SCALE);   // |v| <= 16384, fits s16
        int c0 = __float2int_rn(cosf(a0) * LUT_SCALE);
        int s1 = __float2int_rn(sinf(a1) * LUT_SCALE);
        int c1 = __float2int_rn(cosf(a1) * LUT_SCALE);
        unsigned w0 = ((unsigned)(unsigned short)(short)c0 << 16) | (unsigned short)(short)s0;
        unsigned w1 = ((unsigned)(unsigned short)(short)c1 << 16) | (unsigned short)(short)s1;
        ((uint2*)g_lut32)[t] = make_uint2(w0, w1);
    } else {
        int e = (bid - 18) * 256 + tid;            // < 262144
        int n  = e & 1023;
        int ip = e >> 10;
        const float S = (float)(4096.0 / 6.283185307179586476925287);
        float2 w = ((const float2*)(W + n * 512))[ip];
        float2 b = ((const float2*)(B + n * 512))[ip];
        float4 v;
        v.x = S / (1.0f + fabsf(w.x));
        v.y = S / (1.0f + fabsf(w.y));
        v.z = S * b.x - 0.5f;                      // fold floor(v)=round(v-0.5) shift
        v.w = S * b.y - 0.5f;
        g_rsbs[e] = v;                             // e = ip*1024 + n
    }
}

// ---------------------------------------------------------------------------
// Packed helpers
// ---------------------------------------------------------------------------

__device__ __forceinline__ unsigned long long fma2_(unsigned long long a,
                                                    unsigned long long b,
                                                    unsigned long long c) {
    unsigned long long d;
    asm("fma.rn.f32x2 %0, %1, %2, %3;" : "=l"(d) : "l"(a), "l"(b), "l"(c));
    return d;
}
__device__ __forceinline__ unsigned long long add2_(unsigned long long a,
                                                    unsigned long long b) {
    unsigned long long d;
    asm("add.rn.f32x2 %0, %1, %2;" : "=l"(d) : "l"(a), "l"(b));
    return d;
}
__device__ __forceinline__ unsigned lds32_(unsigned a) {
    unsigned v;
    asm("ld.shared.b32 %0, [%1];" : "=r"(v) : "r"(a));
    return v;
}
// dp2a.lo: d = a.h0*b.b0 + a.h1*b.b1 + c  (16-bit halves of a, low 2 bytes of b)
__device__ __forceinline__ int dp2a_(unsigned a, unsigned b, int c) {
    int d;
    asm("dp2a.lo.s32.s32 %0, %1, %2, %3;" : "=r"(d) : "r"(a), "r"(b), "r"(c));
    return d;
}

// ---------------------------------------------------------------------------
// k_main v5: schedule identical to proven R9/R10 (296 blocks, strided 1024
// fine tiles, thread = 1 neuron x 4 batches, int16 LUT via LDS.32).
// ONLY change: pipe rebalance of the accumulation — build {s0,s1} and
// {c0,c1} with PRMT (alu pipe) and accumulate each with ONE dp2a
// (b=0x0101 -> d = h0 + h1 + c, integer-exact). Moves 2 ops/iter off the
// fma pipe onto the idle alu pipe; numerics bit-identical.
// ---------------------------------------------------------------------------

__global__ __launch_bounds__(256, 2) void k_main(const float* __restrict__ x) {
    extern __shared__ unsigned char smem[];
    uint4* lutv = (uint4*)smem;
    unsigned long long* xs2 = (unsigned long long*)(smem + LUT_N * 4);  // [4 b][64 ip]

    const int tid = threadIdx.x;

#pragma unroll
    for (int t = 0; t < (LUT_N / 4) / 256; t++)        // stage 36KB LUT (9 iters)
        lutv[tid + t * 256] = ((const uint4*)g_lut32)[tid + t * 256];

    const unsigned cbase =
        (unsigned)__cvta_generic_to_shared(smem) + (unsigned)(LUT_HALF * 4) - 0x2D000000u;
    const unsigned long long MAGIC2 = 0x4B4000004B400000ULL;
    const unsigned ONES = 0x0101u;        // dp2a: +1 weights for both halves

    const int lb  = tid >> 6;            // x-loader batch 0..3
    const int ipl = tid & 63;            // x-loader ipair 0..63

    for (int t = blockIdx.x; t < 1024; t += 296) {
        const int nt = t & 3;
        const int iq = (t >> 2) & 3;     // i-quarter (64 ipairs)
        const int bg = t >> 4;           // batch group of 4 (0..63)

        __syncthreads();                 // protect xs2 readers of previous tile
        xs2[tid] = ((const unsigned long long*)x)[((bg << 2) + lb) * 256 + (iq << 6) + ipl];
        __syncthreads();

        const int n = (nt << 8) + tid;
        const ulonglong2* rb =
            (const ulonglong2*)g_rsbs + (size_t)(iq << 6) * 1024 + n;

        int accS[4], accC[4];
#pragma unroll
        for (int b = 0; b < 4; b++) { accS[b] = 0; accC[b] = 0; }

#pragma unroll 2
        for (int ip = 0; ip < 64; ip++) {
            ulonglong2 rv = __ldg(rb + ip * 1024);    // {rs0,rs1},{bs0,bs1}
#pragma unroll
            for (int b = 0; b < 4; b++) {
                unsigned long long xp = xs2[(b << 6) + ip];   // bcast LDS.64
                unsigned long long w  = add2_(fma2_(xp, rv.x, rv.y), MAGIC2);
                unsigned qlo, qhi;
                asm("mov.b64 {%0, %1}, %2;" : "=r"(qlo), "=r"(qhi) : "l"(w));
                unsigned e0 = lds32_(qlo * 4u + cbase);       // {cos16|sin16}
                unsigned e1 = lds32_(qhi * 4u + cbase);
                unsigned ss, cc;
                asm("prmt.b32 %0, %1, %2, 0x5410;" : "=r"(ss) : "r"(e0), "r"(e1)); // {s0,s1}
                asm("prmt.b32 %0, %1, %2, 0x7632;" : "=r"(cc) : "r"(e0), "r"(e1)); // {c0,c1}
                accS[b] = dp2a_(ss, ONES, accS[b]);           // += s0 + s1 (exact)
                accC[b] = dp2a_(cc, ONES, accC[b]);           // += c0 + c1 (exact)
            }
        }

        int2* sp = g_sums + (size_t)iq * 262144 + (size_t)(bg << 2) * 1024 + n;
#pragma unroll
        for (int b = 0; b < 4; b++) sp[(size_t)b * 1024] = make_int2(accS[b], accC[b]);
    }
}

// ---------------------------------------------------------------------------
// k_comb (UNCHANGED — proven): integer-sum 4 quarters exactly, scale once.
// ---------------------------------------------------------------------------

__global__ void k_comb() {
    int e = blockIdx.x * 256 + threadIdx.x;            // < 131072 int4s/quarter
    const int4* p0 = (const int4*)g_sums;              // {s0,c0,s1,c1}
    const int4* p1 = (const int4*)(g_sums + 262144);
    const int4* p2 = (const int4*)(g_sums + 2 * 262144);
    const int4* p3 = (const int4*)(g_sums + 3 * 262144);
    int4 a = p0[e], b = p1[e], c = p2[e], d = p3[e];
    int s0 = (a.x + b.x) + (c.x + d.x);
    int c0 = (a.y + b.y) + (c.y + d.y);
    int s1 = (a.z + b.z) + (c.z + d.z);
    int c1 = (a.w + b.w) + (c.w + d.w);
    const float SC = 1.0f / LUT_SCALE;
    ((float2*)g_A)[e]            = make_float2((float)c0 * SC, (float)c1 * SC); // cos
    ((float2*)(g_A + 262144))[e] = make_float2((float)s0 * SC, (float)s1 * SC); // sin
}

// ---------------------------------------------------------------------------
// k_gemm4 v2: EXACT R10 structure (proven 24.0us: scalar FFMA 4x4 microtile,
// double-buffered, one sync per chunk, outer `#pragma unroll 1`, 8 K-splits)
// with ONE change: __launch_bounds__(256, 4) — forces <=64 regs so 4 blocks
// fit per SM: 32 warps (occ 31%->42%) AND the 512-block grid becomes a
// SINGLE wave (4*148=592 >= 512), removing 2-wave quantization.
// ---------------------------------------------------------------------------

#define BK 16
#define LDP 68    // smem row stride in floats (float4-aligned)

__global__ __launch_bounds__(256, 4) void k_gemm4(const float* __restrict__ Wr,
                                                  const float* __restrict__ Wi) {
    __shared__ float As[2][BK][LDP];
    __shared__ float Bs[2][BK][LDP];

    const int tid = threadIdx.x;
    const int b0 = blockIdx.x << 6;
    const int o0 = blockIdx.y << 6;
    const int z  = blockIdx.z;
    const int pp = z >> 3;               // 0=real(cos), 1=imag(sin)
    const int s  = z & 7;                // K-split (128 each)

    const float* Ap = g_A + pp * 262144;
    const float* Wp = pp ? Wi : Wr;

    const int tx = tid & 15, ty = tid >> 4;
    const int lk = tid & 15;             // k within chunk
    const int lm = tid >> 4;             // base row 0..15 (4 strided rows)
    const int kbase = s << 7;

    float ar[4], br[4];
#pragma unroll
    for (int t = 0; t < 4; t++) {
        ar[t] = Ap[(size_t)(b0 + lm + t * 16) * 1024 + kbase + lk];
        br[t] = Wp[(size_t)(o0 + lm + t * 16) * 1024 + kbase + lk];
    }
#pragma unroll
    for (int t = 0; t < 4; t++) {
        As[0][lk][lm + t * 16] = ar[t];
        Bs[0][lk][lm + t * 16] = br[t];
    }
    __syncthreads();

    float acc[4][4] = {};

#pragma unroll 1
    for (int kc = 0; kc < 8; kc++) {
        const int cur = kc & 1;
        if (kc < 7) {                     // prefetch next chunk into registers
            const int k0 = kbase + ((kc + 1) << 4);
#pragma unroll
            for (int t = 0; t < 4; t++) {
                ar[t] = Ap[(size_t)(b0 + lm + t * 16) * 1024 + k0 + lk];
                br[t] = Wp[(size_t)(o0 + lm + t * 16) * 1024 + k0 + lk];
            }
        }
#pragma unroll
        for (int kk = 0; kk < BK; kk++) {
            float4 a4 = *(const float4*)&As[cur][kk][ty << 2];  // warp broadcast
            float4 b4 = *(const float4*)&Bs[cur][kk][tx << 2];
            float av[4] = {a4.x, a4.y, a4.z, a4.w};
            float bv[4] = {b4.x, b4.y, b4.z, b4.w};
#pragma unroll
            for (int i = 0; i < 4; i++)
#pragma unroll
                for (int j = 0; j < 4; j++)
                    acc[i][j] = fmaf(av[i], bv[j], acc[i][j]);
        }
        if (kc < 7) {
            const int nxt = cur ^ 1;
#pragma unroll
            for (int t = 0; t < 4; t++) {
                As[nxt][lk][lm + t * 16] = ar[t];
                Bs[nxt][lk][lm + t * 16] = br[t];
            }
            __syncthreads();              // one barrier per chunk
        }
    }

    float* dst = &g_part[s][pp * 131072 + (size_t)(b0 + (ty << 2)) * 512 + o0 + (tx << 2)];
#pragma unroll
    for (int i = 0; i < 4; i++)
        *(float4*)(dst + (size_t)i * 512) =
            make_float4(acc[i][0], acc[i][1], acc[i][2], acc[i][3]);
}

// ---------------------------------------------------------------------------
// k_reduce (UNCHANGED — proven R10): 8-way, float4-vectorized, fixed order.
// ---------------------------------------------------------------------------

__global__ void k_reduce(float* __restrict__ out) {
    int e = blockIdx.x * 256 + threadIdx.x;     // < 65536 float4s
    float4 p0 = ((const float4*)g_part[0])[e];
    float4 p1 = ((const float4*)g_part[1])[e];
    float4 p2 = ((const float4*)g_part[2])[e];
    float4 p3 = ((const float4*)g_part[3])[e];
    float4 p4 = ((const float4*)g_part[4])[e];
    float4 p5 = ((const float4*)g_part[5])[e];
    float4 p6 = ((const float4*)g_part[6])[e];
    float4 p7 = ((const float4*)g_part[7])[e];
    float4 r;
    r.x = ((p0.x + p1.x) + (p2.x + p3.x)) + ((p4.x + p5.x) + (p6.x + p7.x));
    r.y = ((p0.y + p1.y) + (p2.y + p3.y)) + ((p4.y + p5.y) + (p6.y + p7.y));
    r.z = ((p0.z + p1.z) + (p2.z + p3.z)) + ((p4.z + p5.z) + (p6.z + p7.z));
    r.w = ((p0.w + p1.w) + (p2.w + p3.w)) + ((p4.w + p5.w) + (p6.w + p7.w));
    ((float4*)out)[e] = r;
}

// ---------------------------------------------------------------------------

extern "C" void kernel_launch(void* const* d_in, const int* in_sizes, int n_in,
                              void* d_out, int out_size) {
    const float* x  = (const float*)d_in[0];
    const float* W  = (const float*)d_in[1];
    const float* B  = (const float*)d_in[2];
    const float* Wr = (const float*)d_in[3];
    const float* Wi = (const float*)d_in[4];
    float* out = (float*)d_out;

    cudaFuncSetAttribute(k_main, cudaFuncAttributeMaxDynamicSharedMemorySize, SMEM_MAIN);

    k_init<<<18 + 1024, 256>>>(W, B);
    k_main<<<296, 256, SMEM_MAIN>>>(x);
    k_comb<<<512, 256>>>();
    k_gemm4<<<dim3(4, 8, 16), 256>>>(Wr, Wi);
    k_reduce<<<256, 256>>>(out);
}

// round 13
// speedup vs baseline: 1.1689x; 1.0876x over previous
#include <cuda_runtime.h>

// ---------------------------------------------------------------------------
// ResonantComplexProjection
//   theta[b,n,i] = x[b,i] / (1+|W[n,i]|) + B[n,i]
//   idx = floor(theta * 4096/2pi) mod 4096   (LUT sin/cos, 4096 entries)
//   cos_sum[b,n] = sum_i cos_lut[idx];  sin_sum likewise
//   real = cos_sum @ Wr^T ; imag = sin_sum @ Wi^T
// Shapes: batch=256, in_f=512, n_neur=1024, out_f=512
// ---------------------------------------------------------------------------

#define LUT_HALF 4608                  // table covers k in [-4608, 4608)
#define LUT_N    (2 * LUT_HALF)        // 9216 packed entries {cos16|sin16}
#define SMEM_MAIN (LUT_N * 4 + 2048)   // 36KB LUT + 2KB x tile = 38912 B
#define LUT_SCALE 16384.0f             // int16 quantization scale (2^14)

static __device__ unsigned g_lut32[LUT_N];     // {(s16)(cos*16384)<<16 | (u16)(s16)(sin*16384)}
static __device__ float4 g_rsbs[256 * 1024];   // [ipair][n] -> {rs0, rs1, bs0, bs1}
static __device__ int2   g_sums[4 * 262144];   // [iq][b][n] -> (sin_acc, cos_acc) int32
static __device__ float  g_A[2 * 262144];      // [p][b][k]: p0=cos, p1=sin
static __device__ float  g_part[8][262144];    // [ksplit][p*131072 + b*512 + o]

// ---------------------------------------------------------------------------
// Fused init: blocks [0,18) build the int16 LUT; blocks [18,1042) build rs/bs.
// ---------------------------------------------------------------------------

__global__ void k_init(const float* __restrict__ W, const float* __restrict__ B) {
    const int bid = blockIdx.x;
    const int tid = threadIdx.x;
    if (bid < 18) {
        int t = bid * 256 + tid;                   // < 4608
        const float step = (float)(6.283185307179586476925287 / 4096.0);
        int k0 = 2 * t - LUT_HALF;
        int j0 = k0 & 4095;                        // floor-mod 4096 (matches Python %)
        int j1 = (k0 + 1) & 4095;
        float a0 = (float)j0 * step;
        float a1 = (float)j1 * step;
        int s0 = __float2int_rn(sinf(a0) * LUT_SCALE);   // |v| <= 16384, fits s16
        int c0 = __float2int_rn(cosf(a0) * LUT_SCALE);
        int s1 = __float2int_rn(sinf(a1) * LUT_SCALE);
        int c1 = __float2int_rn(cosf(a1) * LUT_SCALE);
        unsigned w0 = ((unsigned)(unsigned short)(short)c0 << 16) | (unsigned short)(short)s0;
        unsigned w1 = ((unsigned)(unsigned short)(short)c1 << 16) | (unsigned short)(short)s1;
        ((uint2*)g_lut32)[t] = make_uint2(w0, w1);
    } else {
        int e = (bid - 18) * 256 + tid;            // < 262144
        int n  = e & 1023;
        int ip = e >> 10;
        const float S = (float)(4096.0 / 6.283185307179586476925287);
        float2 w = ((const float2*)(W + n * 512))[ip];
        float2 b = ((const float2*)(B + n * 512))[ip];
        float4 v;
        v.x = S / (1.0f + fabsf(w.x));
        v.y = S / (1.0f + fabsf(w.y));
        v.z = S * b.x - 0.5f;                      // fold floor(v)=round(v-0.5) shift
        v.w = S * b.y - 0.5f;
        g_rsbs[e] = v;                             // e = ip*1024 + n
    }
}

// ---------------------------------------------------------------------------
// Packed helpers
// ---------------------------------------------------------------------------

__device__ __forceinline__ unsigned long long fma2_(unsigned long long a,
                                                    unsigned long long b,
                                                    unsigned long long c) {
    unsigned long long d;
    asm("fma.rn.f32x2 %0, %1, %2, %3;" : "=l"(d) : "l"(a), "l"(b), "l"(c));
    return d;
}
__device__ __forceinline__ unsigned long long add2_(unsigned long long a,
                                                    unsigned long long b) {
    unsigned long long d;
    asm("add.rn.f32x2 %0, %1, %2;" : "=l"(d) : "l"(a), "l"(b));
    return d;
}
__device__ __forceinline__ unsigned lds32_(unsigned a) {
    unsigned v;
    asm("ld.shared.b32 %0, [%1];" : "=r"(v) : "r"(a));
    return v;
}
// dp2a.lo: d = a.h0*b.b0 + a.h1*b.b1 + c  (16-bit halves of a, low 2 bytes of b)
__device__ __forceinline__ int dp2a_(unsigned a, unsigned b, int c) {
    int d;
    asm("dp2a.lo.s32.s32 %0, %1, %2, %3;" : "=r"(d) : "r"(a), "r"(b), "r"(c));
    return d;
}

// ---------------------------------------------------------------------------
// k_main v6: schedule and math identical to proven R11 (296 blocks, strided
// 1024 fine tiles, thread = 1 neuron x 4 batches, int16 LUT via LDS.32,
// prmt+dp2a exact accumulation).
// ONLY change: process TWO consecutive ip per step — the two x-pairs for
// (ip, ip+1) come from ONE LDS.128 broadcast instead of two LDS.64
// broadcasts (same bytes, half the issue slots and half the broadcast
// crossbar cycles), and `#pragma unroll 2` now keeps 4 rv-LDG.128s in
// flight against L2 latency. Integer accumulation is exact and
// order-independent -> bitwise-identical results.
// ---------------------------------------------------------------------------

__global__ __launch_bounds__(256, 2) void k_main(const float* __restrict__ x) {
    extern __shared__ unsigned char smem[];
    uint4* lutv = (uint4*)smem;
    unsigned long long* xs2 = (unsigned long long*)(smem + LUT_N * 4);  // [4 b][64 ip]

    const int tid = threadIdx.x;

#pragma unroll
    for (int t = 0; t < (LUT_N / 4) / 256; t++)        // stage 36KB LUT (9 iters)
        lutv[tid + t * 256] = ((const uint4*)g_lut32)[tid + t * 256];

    const unsigned cbase =
        (unsigned)__cvta_generic_to_shared(smem) + (unsigned)(LUT_HALF * 4) - 0x2D000000u;
    const unsigned long long MAGIC2 = 0x4B4000004B400000ULL;
    const unsigned ONES = 0x0101u;        // dp2a: +1 weights for both halves

    const int lb  = tid >> 6;            // x-loader batch 0..3
    const int ipl = tid & 63;            // x-loader ipair 0..63

    for (int t = blockIdx.x; t < 1024; t += 296) {
        const int nt = t & 3;
        const int iq = (t >> 2) & 3;     // i-quarter (64 ipairs)
        const int bg = t >> 4;           // batch group of 4 (0..63)

        __syncthreads();                 // protect xs2 readers of previous tile
        xs2[tid] = ((const unsigned long long*)x)[((bg << 2) + lb) * 256 + (iq << 6) + ipl];
        __syncthreads();

        const int n = (nt << 8) + tid;
        const ulonglong2* rb =
            (const ulonglong2*)g_rsbs + (size_t)(iq << 6) * 1024 + n;

        int accS[4], accC[4];
#pragma unroll
        for (int b = 0; b < 4; b++) { accS[b] = 0; accC[b] = 0; }

#pragma unroll 2
        for (int ip = 0; ip < 64; ip += 2) {
            ulonglong2 rv0 = __ldg(rb + ip * 1024);        // {rs0,rs1},{bs0,bs1}
            ulonglong2 rv1 = __ldg(rb + (ip + 1) * 1024);
#pragma unroll
            for (int b = 0; b < 4; b++) {
                // ONE LDS.128 broadcast fetches x-pairs for ip and ip+1
                ulonglong2 xp2 = *(const ulonglong2*)&xs2[(b << 6) + ip];

                unsigned long long w0 = add2_(fma2_(xp2.x, rv0.x, rv0.y), MAGIC2);
                unsigned q0l, q0h;
                asm("mov.b64 {%0, %1}, %2;" : "=r"(q0l), "=r"(q0h) : "l"(w0));
                unsigned e0 = lds32_(q0l * 4u + cbase);    // {cos16|sin16}
                unsigned e1 = lds32_(q0h * 4u + cbase);
                unsigned ss0, cc0;
                asm("prmt.b32 %0, %1, %2, 0x5410;" : "=r"(ss0) : "r"(e0), "r"(e1));
                asm("prmt.b32 %0, %1, %2, 0x7632;" : "=r"(cc0) : "r"(e0), "r"(e1));
                accS[b] = dp2a_(ss0, ONES, accS[b]);
                accC[b] = dp2a_(cc0, ONES, accC[b]);

                unsigned long long w1 = add2_(fma2_(xp2.y, rv1.x, rv1.y), MAGIC2);
                unsigned q1l, q1h;
                asm("mov.b64 {%0, %1}, %2;" : "=r"(q1l), "=r"(q1h) : "l"(w1));
                unsigned e2 = lds32_(q1l * 4u + cbase);
                unsigned e3 = lds32_(q1h * 4u + cbase);
                unsigned ss1, cc1;
                asm("prmt.b32 %0, %1, %2, 0x5410;" : "=r"(ss1) : "r"(e2), "r"(e3));
                asm("prmt.b32 %0, %1, %2, 0x7632;" : "=r"(cc1) : "r"(e2), "r"(e3));
                accS[b] = dp2a_(ss1, ONES, accS[b]);
                accC[b] = dp2a_(cc1, ONES, accC[b]);
            }
        }

        int2* sp = g_sums + (size_t)iq * 262144 + (size_t)(bg << 2) * 1024 + n;
#pragma unroll
        for (int b = 0; b < 4; b++) sp[(size_t)b * 1024] = make_int2(accS[b], accC[b]);
    }
}

// ---------------------------------------------------------------------------
// k_comb (UNCHANGED — proven): integer-sum 4 quarters exactly, scale once.
// ---------------------------------------------------------------------------

__global__ void k_comb() {
    int e = blockIdx.x * 256 + threadIdx.x;            // < 131072 int4s/quarter
    const int4* p0 = (const int4*)g_sums;              // {s0,c0,s1,c1}
    const int4* p1 = (const int4*)(g_sums + 262144);
    const int4* p2 = (const int4*)(g_sums + 2 * 262144);
    const int4* p3 = (const int4*)(g_sums + 3 * 262144);
    int4 a = p0[e], b = p1[e], c = p2[e], d = p3[e];
    int s0 = (a.x + b.x) + (c.x + d.x);
    int c0 = (a.y + b.y) + (c.y + d.y);
    int s1 = (a.z + b.z) + (c.z + d.z);
    int c1 = (a.w + b.w) + (c.w + d.w);
    const float SC = 1.0f / LUT_SCALE;
    ((float2*)g_A)[e]            = make_float2((float)c0 * SC, (float)c1 * SC); // cos
    ((float2*)(g_A + 262144))[e] = make_float2((float)s0 * SC, (float)s1 * SC); // sin
}

// ---------------------------------------------------------------------------
// k_gemm4 (UNCHANGED — proven R11): scalar FFMA 4x4 microtile, double-
// buffered, one sync per chunk, outer `#pragma unroll 1`, 8 K-splits,
// __launch_bounds__(256,4) -> 64 regs, single wave.
// ---------------------------------------------------------------------------

#define BK 16
#define LDP 68    // smem row stride in floats (float4-aligned)

__global__ __launch_bounds__(256, 4) void k_gemm4(const float* __restrict__ Wr,
                                                  const float* __restrict__ Wi) {
    __shared__ float As[2][BK][LDP];
    __shared__ float Bs[2][BK][LDP];

    const int tid = threadIdx.x;
    const int b0 = blockIdx.x << 6;
    const int o0 = blockIdx.y << 6;
    const int z  = blockIdx.z;
    const int pp = z >> 3;               // 0=real(cos), 1=imag(sin)
    const int s  = z & 7;                // K-split (128 each)

    const float* Ap = g_A + pp * 262144;
    const float* Wp = pp ? Wi : Wr;

    const int tx = tid & 15, ty = tid >> 4;
    const int lk = tid & 15;             // k within chunk
    const int lm = tid >> 4;             // base row 0..15 (4 strided rows)
    const int kbase = s << 7;

    float ar[4], br[4];
#pragma unroll
    for (int t = 0; t < 4; t++) {
        ar[t] = Ap[(size_t)(b0 + lm + t * 16) * 1024 + kbase + lk];
        br[t] = Wp[(size_t)(o0 + lm + t * 16) * 1024 + kbase + lk];
    }
#pragma unroll
    for (int t = 0; t < 4; t++) {
        As[0][lk][lm + t * 16] = ar[t];
        Bs[0][lk][lm + t * 16] = br[t];
    }
    __syncthreads();

    float acc[4][4] = {};

#pragma unroll 1
    for (int kc = 0; kc < 8; kc++) {
        const int cur = kc & 1;
        if (kc < 7) {                     // prefetch next chunk into registers
            const int k0 = kbase + ((kc + 1) << 4);
#pragma unroll
            for (int t = 0; t < 4; t++) {
                ar[t] = Ap[(size_t)(b0 + lm + t * 16) * 1024 + k0 + lk];
                br[t] = Wp[(size_t)(o0 + lm + t * 16) * 1024 + k0 + lk];
            }
        }
#pragma unroll
        for (int kk = 0; kk < BK; kk++) {
            float4 a4 = *(const float4*)&As[cur][kk][ty << 2];  // warp broadcast
            float4 b4 = *(const float4*)&Bs[cur][kk][tx << 2];
            float av[4] = {a4.x, a4.y, a4.z, a4.w};
            float bv[4] = {b4.x, b4.y, b4.z, b4.w};
#pragma unroll
            for (int i = 0; i < 4; i++)
#pragma unroll
                for (int j = 0; j < 4; j++)
                    acc[i][j] = fmaf(av[i], bv[j], acc[i][j]);
        }
        if (kc < 7) {
            const int nxt = cur ^ 1;
#pragma unroll
            for (int t = 0; t < 4; t++) {
                As[nxt][lk][lm + t * 16] = ar[t];
                Bs[nxt][lk][lm + t * 16] = br[t];
            }
            __syncthreads();              // one barrier per chunk
        }
    }

    float* dst = &g_part[s][pp * 131072 + (size_t)(b0 + (ty << 2)) * 512 + o0 + (tx << 2)];
#pragma unroll
    for (int i = 0; i < 4; i++)
        *(float4*)(dst + (size_t)i * 512) =
            make_float4(acc[i][0], acc[i][1], acc[i][2], acc[i][3]);
}

// ---------------------------------------------------------------------------
// k_reduce (UNCHANGED — proven): 8-way, float4-vectorized, fixed order.
// ---------------------------------------------------------------------------

__global__ void k_reduce(float* __restrict__ out) {
    int e = blockIdx.x * 256 + threadIdx.x;     // < 65536 float4s
    float4 p0 = ((const float4*)g_part[0])[e];
    float4 p1 = ((const float4*)g_part[1])[e];
    float4 p2 = ((const float4*)g_part[2])[e];
    float4 p3 = ((const float4*)g_part[3])[e];
    float4 p4 = ((const float4*)g_part[4])[e];
    float4 p5 = ((const float4*)g_part[5])[e];
    float4 p6 = ((const float4*)g_part[6])[e];
    float4 p7 = ((const float4*)g_part[7])[e];
    float4 r;
    r.x = ((p0.x + p1.x) + (p2.x + p3.x)) + ((p4.x + p5.x) + (p6.x + p7.x));
    r.y = ((p0.y + p1.y) + (p2.y + p3.y)) + ((p4.y + p5.y) + (p6.y + p7.y));
    r.z = ((p0.z + p1.z) + (p2.z + p3.z)) + ((p4.z + p5.z) + (p6.z + p7.z));
    r.w = ((p0.w + p1.w) + (p2.w + p3.w)) + ((p4.w + p5.w) + (p6.w + p7.w));
    ((float4*)out)[e] = r;
}

// ---------------------------------------------------------------------------

extern "C" void kernel_launch(void* const* d_in, const int* in_sizes, int n_in,
                              void* d_out, int out_size) {
    const float* x  = (const float*)d_in[0];
    const float* W  = (const float*)d_in[1];
    const float* B  = (const float*)d_in[2];
    const float* Wr = (const float*)d_in[3];
    const float* Wi = (const float*)d_in[4];
    float* out = (float*)d_out;

    cudaFuncSetAttribute(k_main, cudaFuncAttributeMaxDynamicSharedMemorySize, SMEM_MAIN);

    k_init<<<18 + 1024, 256>>>(W, B);
    k_main<<<296, 256, SMEM_MAIN>>>(x);
    k_comb<<<512, 256>>>();
    k_gemm4<<<dim3(4, 8, 16), 256>>>(Wr, Wi);
    k_reduce<<<256, 256>>>(out);
}